// round 3
// baseline (speedup 1.0000x reference)
#include <cuda_runtime.h>

// ---------------------------------------------------------------------------
// MultiHeadAttentionEdge — reformulated:
//   qk[b,n,h,i] = sum_o (q[b,n,h,o]/sqrt(32)) * Wk[h,i,o]     (i in [0,192))
//   logits[b,h,n,m] = sum_{i<128} qk*key[b,m,i] + sum_{i<64} qk[128+i]*edge[b,n,m,i]
//   attn = softmax_m; mh = attn @ v; out = mh @ Wp + bias
// All fp32. Inner GEMM uses packed fma.rn.f32x2 (two m's per lane-pair).
// ---------------------------------------------------------------------------

namespace {
constexpr int B    = 2;
constexpr int N    = 512;
constexpr int M    = 512;
constexpr int DQ   = 128;
constexpr int DK   = 128;
constexpr int DE   = 64;
constexpr int DKE  = DK + DE;   // 192
constexpr int H    = 8;
constexpr int O    = 32;
constexpr int OUTD = 128;
}

// Scratch (device globals — no allocation allowed)
__device__ float g_qk  [(size_t)B*N*H*DKE];   // 6.3 MB
__device__ float g_v   [(size_t)B*M*H*O];     // 2 MB
__device__ float g_attn[(size_t)B*H*N*M];     // 16.8 MB
__device__ float g_mh  [(size_t)B*N*H*O];     // 2 MB

typedef unsigned long long u64;

__device__ __forceinline__ u64 pack2(float lo, float hi) {
    u64 r; asm("mov.b64 %0, {%1,%2};" : "=l"(r) : "f"(lo), "f"(hi)); return r;
}
__device__ __forceinline__ void fma2(u64& d, u64 a, u64 b) {
    asm("fma.rn.f32x2 %0, %1, %2, %0;" : "+l"(d) : "l"(a), "l"(b));
}
__device__ __forceinline__ float2 unpack2(u64 v) {
    float2 r; asm("mov.b64 {%0,%1}, %2;" : "=f"(r.x), "=f"(r.y) : "l"(v)); return r;
}

// ---------------------------------------------------------------------------
// K1a: per (b, 8-n tile): q = query@Wq / sqrt(32);  qk = q @ Wk^T(over o)
// ---------------------------------------------------------------------------
__global__ __launch_bounds__(256) void k_qk(const float* __restrict__ query,
                                            const float* __restrict__ Wq,
                                            const float* __restrict__ Wk) {
    const int b  = blockIdx.x >> 6;          // 64 tiles per batch
    const int n0 = (blockIdx.x & 63) << 3;
    const int t  = threadIdx.x;

    __shared__ float xs[8][DQ];      // 8 query rows
    __shared__ float qs[8][H*O];     // 8 q rows (h*32+o)

    #pragma unroll
    for (int j = 0; j < 4; j++) {
        int idx = t + 256*j;
        int nl = idx >> 7, d = idx & 127;
        xs[nl][d] = query[((size_t)(b*N + n0 + nl))*DQ + d];
    }
    __syncthreads();

    {   // q: thread owns (h,o), 8 n accumulators; Wq read once per thread
        const int h = t >> 5, o = t & 31;
        float acc[8];
        #pragma unroll
        for (int nl = 0; nl < 8; nl++) acc[nl] = 0.f;
        const float* wq = Wq + ((size_t)h*DQ)*O + o;
        for (int d = 0; d < DQ; d++) {
            float w = wq[(size_t)d*O];
            #pragma unroll
            for (int nl = 0; nl < 8; nl++) acc[nl] = fmaf(xs[nl][d], w, acc[nl]);
        }
        const float scale = 0.17677669529663688f; // 1/sqrt(32)
        #pragma unroll
        for (int nl = 0; nl < 8; nl++) qs[nl][t] = acc[nl] * scale;
    }
    __syncthreads();

    // qk: 1536 (h,i) pairs, 6 per thread, 8 n each
    #pragma unroll
    for (int j = 0; j < 6; j++) {
        int p = t + 256*j;
        int h = p / DKE, i = p - h*DKE;
        const float* wk = Wk + ((size_t)h*DKE + i)*O;
        float acc[8];
        #pragma unroll
        for (int nl = 0; nl < 8; nl++) acc[nl] = 0.f;
        for (int o = 0; o < O; o++) {
            float w = wk[o];
            #pragma unroll
            for (int nl = 0; nl < 8; nl++) acc[nl] = fmaf(qs[nl][h*O + o], w, acc[nl]);
        }
        #pragma unroll
        for (int nl = 0; nl < 8; nl++)
            g_qk[(((size_t)(b*N + n0 + nl))*H + h)*DKE + i] = acc[nl];
    }
}

// ---------------------------------------------------------------------------
// K1b: v[b,m,h,o] = value @ Wv, per (b, 8-m tile)
// ---------------------------------------------------------------------------
__global__ __launch_bounds__(256) void k_v(const float* __restrict__ value,
                                           const float* __restrict__ Wv) {
    const int b  = blockIdx.x >> 6;
    const int m0 = (blockIdx.x & 63) << 3;
    const int t  = threadIdx.x;

    __shared__ float xs[8][DK];
    #pragma unroll
    for (int j = 0; j < 4; j++) {
        int idx = t + 256*j;
        int ml = idx >> 7, d = idx & 127;
        xs[ml][d] = value[((size_t)(b*M + m0 + ml))*DK + d];
    }
    __syncthreads();

    const int h = t >> 5, o = t & 31;
    float acc[8];
    #pragma unroll
    for (int ml = 0; ml < 8; ml++) acc[ml] = 0.f;
    const float* wv = Wv + ((size_t)h*DK)*O + o;
    for (int d = 0; d < DK; d++) {
        float w = wv[(size_t)d*O];
        #pragma unroll
        for (int ml = 0; ml < 8; ml++) acc[ml] = fmaf(xs[ml][d], w, acc[ml]);
    }
    #pragma unroll
    for (int ml = 0; ml < 8; ml++)
        g_v[(((size_t)(b*M + m0 + ml))*H + h)*O + o] = acc[ml];
}

// ---------------------------------------------------------------------------
// K2: per (b,n): logits over all 8 heads & 512 m, softmax, write attn.
//     Thread t owns m-pair (t, t+256) packed into f32x2 lanes.
//     qk is pre-replicated {q,q} in smem so FFMA2 needs no per-op packing.
// ---------------------------------------------------------------------------
__global__ __launch_bounds__(256) void k_attn(const float* __restrict__ key,
                                              const float* __restrict__ edge) {
    const int b = blockIdx.x >> 9;
    const int n = blockIdx.x & 511;
    const int t = threadIdx.x;

    __shared__ u64   qk2[H*DKE];   // 12 KB, replicated pairs
    __shared__ float lg[H][M];     // 16 KB
    __shared__ float rinv[H];

    const float* qkp = g_qk + (size_t)blockIdx.x * (H*DKE);
    #pragma unroll
    for (int j = 0; j < 6; j++) {
        int idx = t + 256*j;
        float v = qkp[idx];
        qk2[idx] = pack2(v, v);
    }
    __syncthreads();

    const int m0 = t, m1 = t + 256;
    u64 acc[H];
    #pragma unroll
    for (int h = 0; h < H; h++) acc[h] = 0ull;

    // --- key phase: i in [0,128) ---
    {
        const float4* r0 = (const float4*)(key + ((size_t)b*M + m0)*DK);
        const float4* r1 = (const float4*)(key + ((size_t)b*M + m1)*DK);
        for (int k4 = 0; k4 < DK/4; k4++) {
            float4 a = r0[k4];
            float4 c = r1[k4];
            u64 p0 = pack2(a.x, c.x), p1 = pack2(a.y, c.y);
            u64 p2 = pack2(a.z, c.z), p3 = pack2(a.w, c.w);
            #pragma unroll
            for (int h = 0; h < H; h++) {
                ulonglong2 qa = *(const ulonglong2*)&qk2[h*DKE + k4*4];
                ulonglong2 qb = *(const ulonglong2*)&qk2[h*DKE + k4*4 + 2];
                fma2(acc[h], qa.x, p0); fma2(acc[h], qa.y, p1);
                fma2(acc[h], qb.x, p2); fma2(acc[h], qb.y, p3);
            }
        }
    }
    // --- edge phase: i in [128,192) ---
    {
        const float4* r0 = (const float4*)(edge + (((size_t)b*N + n)*M + m0)*DE);
        const float4* r1 = (const float4*)(edge + (((size_t)b*N + n)*M + m1)*DE);
        for (int k4 = 0; k4 < DE/4; k4++) {
            float4 a = r0[k4];
            float4 c = r1[k4];
            u64 p0 = pack2(a.x, c.x), p1 = pack2(a.y, c.y);
            u64 p2 = pack2(a.z, c.z), p3 = pack2(a.w, c.w);
            #pragma unroll
            for (int h = 0; h < H; h++) {
                ulonglong2 qa = *(const ulonglong2*)&qk2[h*DKE + DK + k4*4];
                ulonglong2 qb = *(const ulonglong2*)&qk2[h*DKE + DK + k4*4 + 2];
                fma2(acc[h], qa.x, p0); fma2(acc[h], qa.y, p1);
                fma2(acc[h], qb.x, p2); fma2(acc[h], qb.y, p3);
            }
        }
    }

    #pragma unroll
    for (int h = 0; h < H; h++) {
        float2 v = unpack2(acc[h]);
        lg[h][m0] = v.x;
        lg[h][m1] = v.y;
    }
    __syncthreads();

    // softmax: warp w handles head h=w (8 warps)
    {
        const int h = t >> 5, l = t & 31;
        float v[16];
        #pragma unroll
        for (int j = 0; j < 16; j++) v[j] = lg[h][l + 32*j];
        float mx = v[0];
        #pragma unroll
        for (int j = 1; j < 16; j++) mx = fmaxf(mx, v[j]);
        #pragma unroll
        for (int s = 16; s > 0; s >>= 1) mx = fmaxf(mx, __shfl_xor_sync(0xffffffffu, mx, s));
        float sum = 0.f;
        #pragma unroll
        for (int j = 0; j < 16; j++) {
            float e = __expf(v[j] - mx);
            lg[h][l + 32*j] = e;
            sum += e;
        }
        #pragma unroll
        for (int s = 16; s > 0; s >>= 1) sum += __shfl_xor_sync(0xffffffffu, sum, s);
        if (l == 0) rinv[h] = 1.f / sum;
    }
    __syncthreads();

    #pragma unroll
    for (int h = 0; h < H; h++) {
        float inv = rinv[h];
        size_t base = (((size_t)b*H + h)*N + n)*M;
        g_attn[base + m0] = lg[h][m0] * inv;
        g_attn[base + m1] = lg[h][m1] * inv;
    }
}

// ---------------------------------------------------------------------------
// K3: mh[b,n,h,o] = sum_m attn[b,h,n,m] * v[b,m,h,o]
//     block = (b, h, 64-n tile); smem-tiled over m
// ---------------------------------------------------------------------------
__global__ __launch_bounds__(256) void k_av() {
    const int x  = blockIdx.x;          // B*H*8 = 128
    const int b  = x >> 6;
    const int h  = (x >> 3) & 7;
    const int n0 = (x & 7) << 6;
    const int t  = threadIdx.x;
    const int o  = t & 31, nb = t >> 5;  // thread owns o, rows nb+8k

    __shared__ float at[64][64];
    __shared__ float vt[64][O];

    float acc[8];
    #pragma unroll
    for (int k = 0; k < 8; k++) acc[k] = 0.f;

    for (int mt = 0; mt < 8; mt++) {
        const int mb = mt << 6;
        #pragma unroll
        for (int j = 0; j < 4; j++) {     // attn tile: 1024 float4
            int idx = t + 256*j;
            int r = idx >> 4, c = idx & 15;
            *(((float4*)at[r]) + c) =
                *(const float4*)(g_attn + (((size_t)b*H + h)*N + n0 + r)*M + mb + c*4);
        }
        #pragma unroll
        for (int j = 0; j < 2; j++) {     // v tile: 512 float4
            int idx = t + 256*j;
            int r = idx >> 3, c = idx & 7;
            *(((float4*)vt[r]) + c) =
                *(const float4*)(g_v + (((size_t)b*M + mb + r)*H + h)*O + c*4);
        }
        __syncthreads();
        for (int m = 0; m < 64; m++) {
            float vv = vt[m][o];
            #pragma unroll
            for (int k = 0; k < 8; k++) acc[k] = fmaf(at[nb + 8*k][m], vv, acc[k]);
        }
        __syncthreads();
    }
    #pragma unroll
    for (int k = 0; k < 8; k++)
        g_mh[(((size_t)b*N + n0 + nb + 8*k)*H + h)*O + o] = acc[k];
}

// ---------------------------------------------------------------------------
// K4: out[b,n,j] = sum_{k=h*32+o} mh[b,n,k] * Wp[k,j] + bias[j]
// ---------------------------------------------------------------------------
__global__ __launch_bounds__(256) void k_proj(const float* __restrict__ Wp,
                                              const float* __restrict__ bias,
                                              float* __restrict__ out) {
    const int b  = blockIdx.x >> 6;
    const int n0 = (blockIdx.x & 63) << 3;
    const int t  = threadIdx.x;

    __shared__ float mh[8][H*O];
    #pragma unroll
    for (int j = 0; j < 8; j++) {
        int idx = t + 256*j;
        int nl = idx >> 8, c = idx & 255;
        mh[nl][c] = g_mh[((size_t)(b*N + n0 + nl))*(H*O) + c];
    }
    __syncthreads();

    const int jj = t & 127, half = t >> 7;
    const float bv = bias[jj];
    #pragma unroll
    for (int pass = 0; pass < 4; pass++) {
        int nl = half + 2*pass;
        float acc = 0.f;
        for (int k = 0; k < H*O; k++)
            acc = fmaf(mh[nl][k], Wp[(size_t)k*OUTD + jj], acc);
        out[((size_t)(b*N + n0 + nl))*OUTD + jj] = acc + bv;
    }
}

// ---------------------------------------------------------------------------
extern "C" void kernel_launch(void* const* d_in, const int* in_sizes, int n_in,
                              void* d_out, int out_size) {
    (void)in_sizes; (void)n_in; (void)out_size;
    const float* query = (const float*)d_in[0];
    const float* key   = (const float*)d_in[1];
    const float* value = (const float*)d_in[2];
    const float* edge  = (const float*)d_in[3];
    const float* Wq    = (const float*)d_in[4];
    const float* Wk    = (const float*)d_in[5];
    const float* Wv    = (const float*)d_in[6];
    const float* Wp    = (const float*)d_in[7];
    const float* bias  = (const float*)d_in[8];
    float* out = (float*)d_out;

    k_qk  <<<B*(N/8),      256>>>(query, Wq, Wk);
    k_v   <<<B*(M/8),      256>>>(value, Wv);
    k_attn<<<B*N,          256>>>(key, edge);
    k_av  <<<B*H*(N/64),   256>>>();
    k_proj<<<B*(N/8),      256>>>(Wp, bias, out);
}

// round 4
// speedup vs baseline: 1.0139x; 1.0139x over previous
#include <cuda_runtime.h>

// ---------------------------------------------------------------------------
// MultiHeadAttentionEdge — reformulated:
//   qk[b,n,h,i] = sum_o (q[b,n,h,o]/sqrt(32)) * Wk[h,i,o]     (i in [0,192))
//   logits[b,h,n,m] = sum_{i<128} qk*key[b,m,i] + sum_{i<64} qk[128+i]*edge[b,n,m,i]
//   attn = softmax_m; mh = attn @ v; out = mh @ Wp + bias
// All fp32. Inner GEMM uses packed fma.rn.f32x2 (two m's per lane-pair).
// ---------------------------------------------------------------------------

namespace {
constexpr int B    = 2;
constexpr int N    = 512;
constexpr int M    = 512;
constexpr int DQ   = 128;
constexpr int DK   = 128;
constexpr int DE   = 64;
constexpr int DKE  = DK + DE;   // 192
constexpr int H    = 8;
constexpr int O    = 32;
constexpr int OUTD = 128;
}

// Scratch (device globals — no allocation allowed)
__device__ float g_qk  [(size_t)B*N*H*DKE];   // 6.3 MB
__device__ float g_v   [(size_t)B*M*H*O];     // 2 MB
__device__ float g_attn[(size_t)B*H*N*M];     // 16.8 MB
__device__ float g_mh  [(size_t)B*N*H*O];     // 2 MB

typedef unsigned long long u64;

__device__ __forceinline__ u64 pack2(float lo, float hi) {
    u64 r; asm("mov.b64 %0, {%1,%2};" : "=l"(r) : "f"(lo), "f"(hi)); return r;
}
__device__ __forceinline__ void fma2(u64& d, u64 a, u64 b) {
    asm("fma.rn.f32x2 %0, %1, %2, %0;" : "+l"(d) : "l"(a), "l"(b));
}
__device__ __forceinline__ float2 unpack2(u64 v) {
    float2 r; asm("mov.b64 {%0,%1}, %2;" : "=f"(r.x), "=f"(r.y) : "l"(v)); return r;
}

// ---------------------------------------------------------------------------
// K1a: per (b, 8-n tile): q = query@Wq / sqrt(32);  qk = q @ Wk^T(over o)
// ---------------------------------------------------------------------------
__global__ __launch_bounds__(256) void k_qk(const float* __restrict__ query,
                                            const float* __restrict__ Wq,
                                            const float* __restrict__ Wk) {
    const int b  = blockIdx.x >> 6;          // 64 tiles per batch
    const int n0 = (blockIdx.x & 63) << 3;
    const int t  = threadIdx.x;

    __shared__ float xs[8][DQ];      // 8 query rows
    __shared__ float qs[8][H*O];     // 8 q rows (h*32+o)

    #pragma unroll
    for (int j = 0; j < 4; j++) {
        int idx = t + 256*j;
        int nl = idx >> 7, d = idx & 127;
        xs[nl][d] = query[((size_t)(b*N + n0 + nl))*DQ + d];
    }
    __syncthreads();

    {   // q: thread owns (h,o), 8 n accumulators; Wq read once per thread
        const int h = t >> 5, o = t & 31;
        float acc[8];
        #pragma unroll
        for (int nl = 0; nl < 8; nl++) acc[nl] = 0.f;
        const float* wq = Wq + ((size_t)h*DQ)*O + o;
        for (int d = 0; d < DQ; d++) {
            float w = wq[(size_t)d*O];
            #pragma unroll
            for (int nl = 0; nl < 8; nl++) acc[nl] = fmaf(xs[nl][d], w, acc[nl]);
        }
        const float scale = 0.17677669529663688f; // 1/sqrt(32)
        #pragma unroll
        for (int nl = 0; nl < 8; nl++) qs[nl][t] = acc[nl] * scale;
    }
    __syncthreads();

    // qk: 1536 (h,i) pairs, 6 per thread, 8 n each
    #pragma unroll
    for (int j = 0; j < 6; j++) {
        int p = t + 256*j;
        int h = p / DKE, i = p - h*DKE;
        const float* wk = Wk + ((size_t)h*DKE + i)*O;
        float acc[8];
        #pragma unroll
        for (int nl = 0; nl < 8; nl++) acc[nl] = 0.f;
        for (int o = 0; o < O; o++) {
            float w = wk[o];
            #pragma unroll
            for (int nl = 0; nl < 8; nl++) acc[nl] = fmaf(qs[nl][h*O + o], w, acc[nl]);
        }
        #pragma unroll
        for (int nl = 0; nl < 8; nl++)
            g_qk[(((size_t)(b*N + n0 + nl))*H + h)*DKE + i] = acc[nl];
    }
}

// ---------------------------------------------------------------------------
// K1b: v[b,m,h,o] = value @ Wv, per (b, 8-m tile)
// ---------------------------------------------------------------------------
__global__ __launch_bounds__(256) void k_v(const float* __restrict__ value,
                                           const float* __restrict__ Wv) {
    const int b  = blockIdx.x >> 6;
    const int m0 = (blockIdx.x & 63) << 3;
    const int t  = threadIdx.x;

    __shared__ float xs[8][DK];
    #pragma unroll
    for (int j = 0; j < 4; j++) {
        int idx = t + 256*j;
        int ml = idx >> 7, d = idx & 127;
        xs[ml][d] = value[((size_t)(b*M + m0 + ml))*DK + d];
    }
    __syncthreads();

    const int h = t >> 5, o = t & 31;
    float acc[8];
    #pragma unroll
    for (int ml = 0; ml < 8; ml++) acc[ml] = 0.f;
    const float* wv = Wv + ((size_t)h*DK)*O + o;
    for (int d = 0; d < DK; d++) {
        float w = wv[(size_t)d*O];
        #pragma unroll
        for (int ml = 0; ml < 8; ml++) acc[ml] = fmaf(xs[ml][d], w, acc[ml]);
    }
    #pragma unroll
    for (int ml = 0; ml < 8; ml++)
        g_v[(((size_t)(b*M + m0 + ml))*H + h)*O + o] = acc[ml];
}

// ---------------------------------------------------------------------------
// K2: per (b,n): logits over all 8 heads & 512 m, softmax, write attn.
//     Thread t owns m-pair (t, t+256) packed into f32x2 lanes.
//     qk is pre-replicated {q,q} in smem so FFMA2 needs no per-op packing.
// ---------------------------------------------------------------------------
__global__ __launch_bounds__(256) void k_attn(const float* __restrict__ key,
                                              const float* __restrict__ edge) {
    const int b = blockIdx.x >> 9;
    const int n = blockIdx.x & 511;
    const int t = threadIdx.x;

    __shared__ u64   qk2[H*DKE];   // 12 KB, replicated pairs
    __shared__ float lg[H][M];     // 16 KB
    __shared__ float rinv[H];

    const float* qkp = g_qk + (size_t)blockIdx.x * (H*DKE);
    #pragma unroll
    for (int j = 0; j < 6; j++) {
        int idx = t + 256*j;
        float v = qkp[idx];
        qk2[idx] = pack2(v, v);
    }
    __syncthreads();

    const int m0 = t, m1 = t + 256;
    u64 acc[H];
    #pragma unroll
    for (int h = 0; h < H; h++) acc[h] = 0ull;

    // --- key phase: i in [0,128) ---
    {
        const float4* r0 = (const float4*)(key + ((size_t)b*M + m0)*DK);
        const float4* r1 = (const float4*)(key + ((size_t)b*M + m1)*DK);
        for (int k4 = 0; k4 < DK/4; k4++) {
            float4 a = r0[k4];
            float4 c = r1[k4];
            u64 p0 = pack2(a.x, c.x), p1 = pack2(a.y, c.y);
            u64 p2 = pack2(a.z, c.z), p3 = pack2(a.w, c.w);
            #pragma unroll
            for (int h = 0; h < H; h++) {
                ulonglong2 qa = *(const ulonglong2*)&qk2[h*DKE + k4*4];
                ulonglong2 qb = *(const ulonglong2*)&qk2[h*DKE + k4*4 + 2];
                fma2(acc[h], qa.x, p0); fma2(acc[h], qa.y, p1);
                fma2(acc[h], qb.x, p2); fma2(acc[h], qb.y, p3);
            }
        }
    }
    // --- edge phase: i in [128,192) ---
    {
        const float4* r0 = (const float4*)(edge + (((size_t)b*N + n)*M + m0)*DE);
        const float4* r1 = (const float4*)(edge + (((size_t)b*N + n)*M + m1)*DE);
        for (int k4 = 0; k4 < DE/4; k4++) {
            float4 a = r0[k4];
            float4 c = r1[k4];
            u64 p0 = pack2(a.x, c.x), p1 = pack2(a.y, c.y);
            u64 p2 = pack2(a.z, c.z), p3 = pack2(a.w, c.w);
            #pragma unroll
            for (int h = 0; h < H; h++) {
                ulonglong2 qa = *(const ulonglong2*)&qk2[h*DKE + DK + k4*4];
                ulonglong2 qb = *(const ulonglong2*)&qk2[h*DKE + DK + k4*4 + 2];
                fma2(acc[h], qa.x, p0); fma2(acc[h], qa.y, p1);
                fma2(acc[h], qb.x, p2); fma2(acc[h], qb.y, p3);
            }
        }
    }

    #pragma unroll
    for (int h = 0; h < H; h++) {
        float2 v = unpack2(acc[h]);
        lg[h][m0] = v.x;
        lg[h][m1] = v.y;
    }
    __syncthreads();

    // softmax: warp w handles head h=w (8 warps)
    {
        const int h = t >> 5, l = t & 31;
        float v[16];
        #pragma unroll
        for (int j = 0; j < 16; j++) v[j] = lg[h][l + 32*j];
        float mx = v[0];
        #pragma unroll
        for (int j = 1; j < 16; j++) mx = fmaxf(mx, v[j]);
        #pragma unroll
        for (int s = 16; s > 0; s >>= 1) mx = fmaxf(mx, __shfl_xor_sync(0xffffffffu, mx, s));
        float sum = 0.f;
        #pragma unroll
        for (int j = 0; j < 16; j++) {
            float e = __expf(v[j] - mx);
            lg[h][l + 32*j] = e;
            sum += e;
        }
        #pragma unroll
        for (int s = 16; s > 0; s >>= 1) sum += __shfl_xor_sync(0xffffffffu, sum, s);
        if (l == 0) rinv[h] = 1.f / sum;
    }
    __syncthreads();

    #pragma unroll
    for (int h = 0; h < H; h++) {
        float inv = rinv[h];
        size_t base = (((size_t)b*H + h)*N + n)*M;
        g_attn[base + m0] = lg[h][m0] * inv;
        g_attn[base + m1] = lg[h][m1] * inv;
    }
}

// ---------------------------------------------------------------------------
// K3: mh[b,n,h,o] = sum_m attn[b,h,n,m] * v[b,m,h,o]
//     block = (b, h, 64-n tile); smem-tiled over m
// ---------------------------------------------------------------------------
__global__ __launch_bounds__(256) void k_av() {
    const int x  = blockIdx.x;          // B*H*8 = 128
    const int b  = x >> 6;
    const int h  = (x >> 3) & 7;
    const int n0 = (x & 7) << 6;
    const int t  = threadIdx.x;
    const int o  = t & 31, nb = t >> 5;  // thread owns o, rows nb+8k

    __shared__ float at[64][64];
    __shared__ float vt[64][O];

    float acc[8];
    #pragma unroll
    for (int k = 0; k < 8; k++) acc[k] = 0.f;

    for (int mt = 0; mt < 8; mt++) {
        const int mb = mt << 6;
        #pragma unroll
        for (int j = 0; j < 4; j++) {     // attn tile: 1024 float4
            int idx = t + 256*j;
            int r = idx >> 4, c = idx & 15;
            *(((float4*)at[r]) + c) =
                *(const float4*)(g_attn + (((size_t)b*H + h)*N + n0 + r)*M + mb + c*4);
        }
        #pragma unroll
        for (int j = 0; j < 2; j++) {     // v tile: 512 float4
            int idx = t + 256*j;
            int r = idx >> 3, c = idx & 7;
            *(((float4*)vt[r]) + c) =
                *(const float4*)(g_v + (((size_t)b*M + mb + r)*H + h)*O + c*4);
        }
        __syncthreads();
        for (int m = 0; m < 64; m++) {
            float vv = vt[m][o];
            #pragma unroll
            for (int k = 0; k < 8; k++) acc[k] = fmaf(at[nb + 8*k][m], vv, acc[k]);
        }
        __syncthreads();
    }
    #pragma unroll
    for (int k = 0; k < 8; k++)
        g_mh[(((size_t)b*N + n0 + nb + 8*k)*H + h)*O + o] = acc[k];
}

// ---------------------------------------------------------------------------
// K4: out[b,n,j] = sum_{k=h*32+o} mh[b,n,k] * Wp[k,j] + bias[j]
// ---------------------------------------------------------------------------
__global__ __launch_bounds__(256) void k_proj(const float* __restrict__ Wp,
                                              const float* __restrict__ bias,
                                              float* __restrict__ out) {
    const int b  = blockIdx.x >> 6;
    const int n0 = (blockIdx.x & 63) << 3;
    const int t  = threadIdx.x;

    __shared__ float mh[8][H*O];
    #pragma unroll
    for (int j = 0; j < 8; j++) {
        int idx = t + 256*j;
        int nl = idx >> 8, c = idx & 255;
        mh[nl][c] = g_mh[((size_t)(b*N + n0 + nl))*(H*O) + c];
    }
    __syncthreads();

    const int jj = t & 127, half = t >> 7;
    const float bv = bias[jj];
    #pragma unroll
    for (int pass = 0; pass < 4; pass++) {
        int nl = half + 2*pass;
        float acc = 0.f;
        for (int k = 0; k < H*O; k++)
            acc = fmaf(mh[nl][k], Wp[(size_t)k*OUTD + jj], acc);
        out[((size_t)(b*N + n0 + nl))*OUTD + jj] = acc + bv;
    }
}

// ---------------------------------------------------------------------------
extern "C" void kernel_launch(void* const* d_in, const int* in_sizes, int n_in,
                              void* d_out, int out_size) {
    (void)in_sizes; (void)n_in; (void)out_size;
    const float* query = (const float*)d_in[0];
    const float* key   = (const float*)d_in[1];
    const float* value = (const float*)d_in[2];
    const float* edge  = (const float*)d_in[3];
    const float* Wq    = (const float*)d_in[4];
    const float* Wk    = (const float*)d_in[5];
    const float* Wv    = (const float*)d_in[6];
    const float* Wp    = (const float*)d_in[7];
    const float* bias  = (const float*)d_in[8];
    float* out = (float*)d_out;

    k_qk  <<<B*(N/8),      256>>>(query, Wq, Wk);
    k_v   <<<B*(M/8),      256>>>(value, Wv);
    k_attn<<<B*N,          256>>>(key, edge);
    k_av  <<<B*H*(N/64),   256>>>();
    k_proj<<<B*(N/8),      256>>>(Wp, bias, out);
}

// round 5
// speedup vs baseline: 1.1135x; 1.0982x over previous
#include <cuda_runtime.h>

// ---------------------------------------------------------------------------
// MultiHeadAttentionEdge — reformulated:
//   qk[b,n,h,i] = sum_o (q[b,n,h,o]/sqrt(32)) * Wk[h,i,o]     (i in [0,192))
//   logits[b,h,n,m] = sum_{i<128} qk_i*key[b,m,i] + sum_{i<64} qk_{128+i}*edge[b,n,m,i]
//   attn = softmax_m; mh = attn @ v; out = mh @ Wp + bias
// R4: full coalescing rewrite. keyT pre-transpose; edge staged through smem
// (32B-sector coalesced loads + pitch-514 transpose); qk in [i][h] layout;
// thread owns adjacent m-pair (2t,2t+1) so key LDG.64 IS the f32x2 operand.
// ---------------------------------------------------------------------------

namespace {
constexpr int B    = 2;
constexpr int N    = 512;
constexpr int M    = 512;
constexpr int DQ   = 128;
constexpr int DK   = 128;
constexpr int DE   = 64;
constexpr int DKE  = DK + DE;   // 192
constexpr int H    = 8;
constexpr int O    = 32;
constexpr int OUTD = 128;
}

// Scratch (device globals — no allocation allowed)
__device__ __align__(16) float g_qk  [(size_t)B*N*DKE*H];   // [b][n][i][h] 6.3 MB
__device__ __align__(16) float g_keyT[(size_t)B*DK*M];      // [b][i][m] 0.5 MB
__device__ __align__(16) float g_v   [(size_t)B*M*H*O];     // [b][m][h][o] 2 MB
__device__ __align__(16) float g_attn[(size_t)B*H*N*M];     // 16.8 MB
__device__ __align__(16) float g_mh  [(size_t)B*N*H*O];     // [b][n][h][o] 2 MB

typedef unsigned long long u64;

__device__ __forceinline__ u64 pack2(float lo, float hi) {
    u64 r; asm("mov.b64 %0, {%1,%2};" : "=l"(r) : "f"(lo), "f"(hi)); return r;
}
__device__ __forceinline__ void fma2(u64& d, u64 a, u64 b) {
    asm("fma.rn.f32x2 %0, %1, %2, %0;" : "+l"(d) : "l"(a), "l"(b));
}
__device__ __forceinline__ float2 unpack2(u64 v) {
    float2 r; asm("mov.b64 {%0,%1}, %2;" : "=f"(r.x), "=f"(r.y) : "l"(v)); return r;
}

// ---------------------------------------------------------------------------
// K0: key transpose -> g_keyT[b][i][m]  (32x32 smem tiles)
// ---------------------------------------------------------------------------
__global__ __launch_bounds__(256) void k_keyT(const float* __restrict__ key) {
    __shared__ float ts[32][33];
    const int x  = blockIdx.x;             // B*16*4 = 128
    const int b  = x >> 6;
    const int mt = (x & 63) >> 2;
    const int it = x & 3;
    const int m0 = mt << 5, i0 = it << 5;
    const int t  = threadIdx.x;
    #pragma unroll
    for (int j = 0; j < 4; j++) {
        int idx = t + 256*j;
        int r = idx >> 5, c = idx & 31;
        ts[r][c] = key[((size_t)b*M + m0 + r)*DK + i0 + c];
    }
    __syncthreads();
    #pragma unroll
    for (int j = 0; j < 4; j++) {
        int idx = t + 256*j;
        int r = idx >> 5, c = idx & 31;
        g_keyT[((size_t)b*DK + i0 + r)*M + m0 + c] = ts[c][r];
    }
}

// ---------------------------------------------------------------------------
// K1a: per (b, 8-n tile): q = query@Wq / sqrt(32);  qk = q @ Wk^T(over o)
//      writes g_qk in [b][n][i][h] layout
// ---------------------------------------------------------------------------
__global__ __launch_bounds__(256) void k_qk(const float* __restrict__ query,
                                            const float* __restrict__ Wq,
                                            const float* __restrict__ Wk) {
    const int b  = blockIdx.x >> 6;
    const int n0 = (blockIdx.x & 63) << 3;
    const int t  = threadIdx.x;

    __shared__ float xs[8][DQ];
    __shared__ float qs[8][H*O];

    #pragma unroll
    for (int j = 0; j < 4; j++) {
        int idx = t + 256*j;
        int nl = idx >> 7, d = idx & 127;
        xs[nl][d] = query[((size_t)(b*N + n0 + nl))*DQ + d];
    }
    __syncthreads();

    {   // q: thread owns (h,o)
        const int h = t >> 5, o = t & 31;
        float acc[8];
        #pragma unroll
        for (int nl = 0; nl < 8; nl++) acc[nl] = 0.f;
        const float* wq = Wq + ((size_t)h*DQ)*O + o;
        for (int d = 0; d < DQ; d++) {
            float w = wq[(size_t)d*O];
            #pragma unroll
            for (int nl = 0; nl < 8; nl++) acc[nl] = fmaf(xs[nl][d], w, acc[nl]);
        }
        const float scale = 0.17677669529663688f; // 1/sqrt(32)
        #pragma unroll
        for (int nl = 0; nl < 8; nl++) qs[nl][t] = acc[nl] * scale;
    }
    __syncthreads();

    // qk: 1536 (h,i) pairs, 6 per thread, 8 n each
    #pragma unroll
    for (int j = 0; j < 6; j++) {
        int p = t + 256*j;
        int h = p / DKE, i = p - h*DKE;
        const float* wk = Wk + ((size_t)h*DKE + i)*O;
        float acc[8];
        #pragma unroll
        for (int nl = 0; nl < 8; nl++) acc[nl] = 0.f;
        for (int o = 0; o < O; o++) {
            float w = wk[o];
            #pragma unroll
            for (int nl = 0; nl < 8; nl++) acc[nl] = fmaf(qs[nl][h*O + o], w, acc[nl]);
        }
        #pragma unroll
        for (int nl = 0; nl < 8; nl++)
            g_qk[((size_t)(b*N + n0 + nl)*DKE + i)*H + h] = acc[nl];
    }
}

// ---------------------------------------------------------------------------
// K1b: v[b,m,h,o] = value @ Wv
// ---------------------------------------------------------------------------
__global__ __launch_bounds__(256) void k_v(const float* __restrict__ value,
                                           const float* __restrict__ Wv) {
    const int b  = blockIdx.x >> 6;
    const int m0 = (blockIdx.x & 63) << 3;
    const int t  = threadIdx.x;

    __shared__ float xs[8][DK];
    #pragma unroll
    for (int j = 0; j < 4; j++) {
        int idx = t + 256*j;
        int ml = idx >> 7, d = idx & 127;
        xs[ml][d] = value[((size_t)(b*M + m0 + ml))*DK + d];
    }
    __syncthreads();

    const int h = t >> 5, o = t & 31;
    float acc[8];
    #pragma unroll
    for (int ml = 0; ml < 8; ml++) acc[ml] = 0.f;
    const float* wv = Wv + ((size_t)h*DK)*O + o;
    for (int d = 0; d < DK; d++) {
        float w = wv[(size_t)d*O];
        #pragma unroll
        for (int ml = 0; ml < 8; ml++) acc[ml] = fmaf(xs[ml][d], w, acc[ml]);
    }
    #pragma unroll
    for (int ml = 0; ml < 8; ml++)
        g_v[(((size_t)(b*M + m0 + ml))*H + h)*O + o] = acc[ml];
}

// ---------------------------------------------------------------------------
// K2: per (b,n): logits (key via coalesced keyT LDG.64 = f32x2 operand;
//     edge via smem transpose), fused softmax, coalesced attn write.
//     Thread owns m-pair (2t, 2t+1); acc[h] packs both m's.
// ---------------------------------------------------------------------------
__global__ __launch_bounds__(256) void k_attn(const float* __restrict__ edge) {
    __shared__ __align__(16) u64   qk2[DKE*H];   // [i][h] replicated {q,q}, 12.3 KB
    __shared__ __align__(16) float xs[8][514];   // edge i-slice transposed, 16.4 KB
    __shared__ __align__(16) float lg[H*M];      // [h][m], 16 KB
    __shared__ float rinv[H];

    const int bn = blockIdx.x;     // b*N + n
    const int b  = bn >> 9;
    const int n  = bn & 511;
    const int t  = threadIdx.x;

    // qk load (coalesced: gmem layout is [i][h] flat) + replicate to pairs
    const float* qkp = g_qk + (size_t)bn * (DKE*H);
    #pragma unroll
    for (int j = 0; j < 6; j++) {
        int idx = t + 256*j;
        float v = qkp[idx];
        qk2[idx] = pack2(v, v);
    }
    __syncthreads();

    u64 acc[H];
    #pragma unroll
    for (int h = 0; h < H; h++) acc[h] = 0ull;

    // ---- key phase: i in [0,128), keyT[b][i][2t..2t+1] is the operand ----
    {
        const u64* kT = (const u64*)(g_keyT + (size_t)b*DK*M) + t;
        #pragma unroll 4
        for (int i = 0; i < DK; i++) {
            u64 p = kT[(size_t)i*(M/2)];
            const ulonglong2* q = (const ulonglong2*)(qk2 + i*H);
            ulonglong2 q0 = q[0], q1 = q[1], q2 = q[2], q3 = q[3];
            fma2(acc[0], q0.x, p); fma2(acc[1], q0.y, p);
            fma2(acc[2], q1.x, p); fma2(acc[3], q1.y, p);
            fma2(acc[4], q2.x, p); fma2(acc[5], q2.y, p);
            fma2(acc[6], q3.x, p); fma2(acc[7], q3.y, p);
        }
    }

    // ---- edge phase: 8 slices of 8 i's, staged+transposed through smem ----
    for (int sub = 0; sub < 8; sub++) {
        __syncthreads();
        #pragma unroll
        for (int j = 0; j < 4; j++) {
            int idx = t + 256*j;            // 0..1023
            int m = idx >> 1, c = idx & 1;  // 2 float4 per m-row slice of 8
            float4 v = *(const float4*)(edge + ((size_t)bn*M + m)*DE + sub*8 + c*4);
            int si = c*4;
            xs[si+0][m] = v.x; xs[si+1][m] = v.y;
            xs[si+2][m] = v.z; xs[si+3][m] = v.w;
        }
        __syncthreads();
        #pragma unroll
        for (int il = 0; il < 8; il++) {
            int i = DK + sub*8 + il;
            u64 p = *(const u64*)(&xs[il][2*t]);
            const ulonglong2* q = (const ulonglong2*)(qk2 + i*H);
            ulonglong2 q0 = q[0], q1 = q[1], q2 = q[2], q3 = q[3];
            fma2(acc[0], q0.x, p); fma2(acc[1], q0.y, p);
            fma2(acc[2], q1.x, p); fma2(acc[3], q1.y, p);
            fma2(acc[4], q2.x, p); fma2(acc[5], q2.y, p);
            fma2(acc[6], q3.x, p); fma2(acc[7], q3.y, p);
        }
    }

    #pragma unroll
    for (int h = 0; h < H; h++) {
        float2 v = unpack2(acc[h]);
        *(float2*)(lg + h*M + 2*t) = v;
    }
    __syncthreads();

    // softmax: warp w handles head h=w
    {
        const int h = t >> 5, l = t & 31;
        float* lh = lg + h*M;
        float v[16];
        #pragma unroll
        for (int j = 0; j < 16; j++) v[j] = lh[l + 32*j];
        float mx = v[0];
        #pragma unroll
        for (int j = 1; j < 16; j++) mx = fmaxf(mx, v[j]);
        #pragma unroll
        for (int s = 16; s > 0; s >>= 1) mx = fmaxf(mx, __shfl_xor_sync(0xffffffffu, mx, s));
        float sum = 0.f;
        #pragma unroll
        for (int j = 0; j < 16; j++) {
            float e = __expf(v[j] - mx);
            lh[l + 32*j] = e;
            sum += e;
        }
        #pragma unroll
        for (int s = 16; s > 0; s >>= 1) sum += __shfl_xor_sync(0xffffffffu, sum, s);
        if (l == 0) rinv[h] = 1.f / sum;
    }
    __syncthreads();

    #pragma unroll
    for (int h = 0; h < H; h++) {
        float inv = rinv[h];
        float2 e = *(const float2*)(lg + h*M + 2*t);
        float2 o2 = make_float2(e.x * inv, e.y * inv);
        *(float2*)(g_attn + (((size_t)b*H + h)*N + n)*M + 2*t) = o2;
    }
}

// ---------------------------------------------------------------------------
// K3: mh[b,n,h,o] = sum_m attn[b,h,n,m] * v[b,m,h,o]
//     256 blocks = (b, h, 32-n tile); m chunks of 128; f32x2 accumulators.
// ---------------------------------------------------------------------------
__global__ __launch_bounds__(256) void k_av() {
    const int x  = blockIdx.x;           // 2*8*16 = 256
    const int b  = x >> 7;
    const int h  = (x >> 4) & 7;
    const int n0 = (x & 15) << 5;
    const int t  = threadIdx.x;
    const int nl = t >> 3;               // 0..31 local n
    const int og = t & 7;                // o-group (4 o's)

    __shared__ __align__(16) float at[32][132];   // pitch 132: conflict-free
    __shared__ __align__(16) float vt[128][32];

    u64 a01 = 0ull, a23 = 0ull;

    for (int mt = 0; mt < 4; mt++) {
        const int mb = mt << 7;
        #pragma unroll
        for (int j = 0; j < 4; j++) {    // attn tile 32x128 = 1024 float4
            int idx = t + 256*j;
            int r = idx >> 5, c = idx & 31;
            *(float4*)&at[r][c*4] =
                *(const float4*)(g_attn + (((size_t)b*H + h)*N + n0 + r)*M + mb + c*4);
        }
        #pragma unroll
        for (int j = 0; j < 4; j++) {    // v tile 128x32 = 1024 float4
            int idx = t + 256*j;
            int ml = idx >> 3, c = idx & 7;
            *(float4*)&vt[ml][c*4] =
                *(const float4*)(g_v + (((size_t)b*M + mb + ml)*H + h)*O + c*4);
        }
        __syncthreads();
        #pragma unroll 4
        for (int m = 0; m < 128; m++) {
            float a = at[nl][m];
            u64 a2 = pack2(a, a);
            const u64* vv = (const u64*)&vt[m][og*4];
            fma2(a01, a2, vv[0]);
            fma2(a23, a2, vv[1]);
        }
        __syncthreads();
    }
    float2 x01 = unpack2(a01), x23 = unpack2(a23);
    float4 outv = make_float4(x01.x, x01.y, x23.x, x23.y);
    *(float4*)&g_mh[((size_t)(b*N + n0 + nl)*H + h)*O + og*4] = outv;
}

// ---------------------------------------------------------------------------
// K4: out[b,n,j] = sum_k mh[b,n,k] * Wp[k,j] + bias[j]
// ---------------------------------------------------------------------------
__global__ __launch_bounds__(256) void k_proj(const float* __restrict__ Wp,
                                              const float* __restrict__ bias,
                                              float* __restrict__ out) {
    const int b  = blockIdx.x >> 6;
    const int n0 = (blockIdx.x & 63) << 3;
    const int t  = threadIdx.x;

    __shared__ float mh[8][H*O];
    #pragma unroll
    for (int j = 0; j < 8; j++) {
        int idx = t + 256*j;
        int nl = idx >> 8, c = idx & 255;
        mh[nl][c] = g_mh[((size_t)(b*N + n0 + nl))*(H*O) + c];
    }
    __syncthreads();

    const int jj = t & 127, half = t >> 7;
    const float bv = bias[jj];
    #pragma unroll
    for (int pass = 0; pass < 4; pass++) {
        int nl = half + 2*pass;
        float acc = 0.f;
        for (int k = 0; k < H*O; k++)
            acc = fmaf(mh[nl][k], Wp[(size_t)k*OUTD + jj], acc);
        out[((size_t)(b*N + n0 + nl))*OUTD + jj] = acc + bv;
    }
}

// ---------------------------------------------------------------------------
extern "C" void kernel_launch(void* const* d_in, const int* in_sizes, int n_in,
                              void* d_out, int out_size) {
    (void)in_sizes; (void)n_in; (void)out_size;
    const float* query = (const float*)d_in[0];
    const float* key   = (const float*)d_in[1];
    const float* value = (const float*)d_in[2];
    const float* edge  = (const float*)d_in[3];
    const float* Wq    = (const float*)d_in[4];
    const float* Wk    = (const float*)d_in[5];
    const float* Wv    = (const float*)d_in[6];
    const float* Wp    = (const float*)d_in[7];
    const float* bias  = (const float*)d_in[8];
    float* out = (float*)d_out;

    k_keyT<<<B*16*4,       256>>>(key);
    k_qk  <<<B*(N/8),      256>>>(query, Wq, Wk);
    k_v   <<<B*(M/8),      256>>>(value, Wv);
    k_attn<<<B*N,          256>>>(edge);
    k_av  <<<B*H*(N/32),   256>>>();
    k_proj<<<B*(N/8),      256>>>(Wp, bias, out);
}